// round 2
// baseline (speedup 1.0000x reference)
#include <cuda_runtime.h>

// Problem constants (fixed for this instance; V passed at runtime for A/Wr strides)
#define DD      4096     // embedding dim
#define RNK     16       // LoRA rank
#define SEQ     512      // sequence length
#define SPLIT   32       // first 32 positions use img router
#define SCALE   2.0f     // lora_alpha / r
#define T_TILE  32       // tokens per block
#define THREADS 256      // threads per block; each owns 4 consecutive d -> 1024-wide d tile

typedef unsigned long long ull;

__device__ __forceinline__ ull pk(float lo, float hi) {
    ull r; asm("mov.b64 %0,{%1,%2};" : "=l"(r) : "f"(lo), "f"(hi)); return r;
}
__device__ __forceinline__ void upk(ull v, float& lo, float& hi) {
    asm("mov.b64 {%0,%1},%2;" : "=f"(lo), "=f"(hi) : "l"(v));
}
// Blackwell packed fp32x2 FMA: d = a*b + c on both halves
__device__ __forceinline__ ull fma2(ull a, ull b, ull c) {
    ull r; asm("fma.rn.f32x2 %0,%1,%2,%3;" : "=l"(r) : "l"(a), "l"(b), "l"(c)); return r;
}

// Load 16-wide rows d0..d0+3 of Bm ([D,16] row-major) and pack cross-row pairs:
// bp[2*j+0] = (Bm[d0][j],   Bm[d0+1][j])
// bp[2*j+1] = (Bm[d0+2][j], Bm[d0+3][j])
__device__ __forceinline__ void load_bpairs(const float* __restrict__ Bm, int d0, ull* bp) {
#pragma unroll
    for (int pr = 0; pr < 2; ++pr) {
        const float4* p0 = reinterpret_cast<const float4*>(Bm + (size_t)(d0 + 2 * pr) * RNK);
        const float4* p1 = reinterpret_cast<const float4*>(Bm + (size_t)(d0 + 2 * pr + 1) * RNK);
        float ra[16], rb[16];
#pragma unroll
        for (int q = 0; q < 4; ++q) {
            float4 v0 = p0[q]; float4 v1 = p1[q];
            ra[4 * q + 0] = v0.x; ra[4 * q + 1] = v0.y; ra[4 * q + 2] = v0.z; ra[4 * q + 3] = v0.w;
            rb[4 * q + 0] = v1.x; rb[4 * q + 1] = v1.y; rb[4 * q + 2] = v1.z; rb[4 * q + 3] = v1.w;
        }
#pragma unroll
        for (int j = 0; j < 16; ++j) bp[2 * j + pr] = pk(ra[j], rb[j]);
    }
}

__global__ __launch_bounds__(THREADS, 1)
void moe_emb_kernel(const int* __restrict__ xg,
                    const float* __restrict__ emb,
                    const float* __restrict__ A1, const float* __restrict__ B1,
                    const float* __restrict__ A2, const float* __restrict__ B2,
                    const float* __restrict__ WrI, const float* __restrict__ brI,
                    const float* __restrict__ WrT, const float* __restrict__ brT,
                    float* __restrict__ out, int V, int n_tok)
{
    __shared__ __align__(16) float scoef[T_TILE * 64];  // 32 coefs/token, each duplicated (c,c)
    __shared__ int   sx[T_TILE];
    __shared__ float sw[T_TILE * 2];

    const int tid = threadIdx.x;
    const int t0  = blockIdx.y * T_TILE;
    const int d0  = blockIdx.x * (THREADS * 4) + tid * 4;

    // ---- load B pair registers early (L2-hot; overlaps phase-1 barrier) ----
    ull bp[64];
    load_bpairs(B1, d0, bp);        // coef slots 0..15
    load_bpairs(B2, d0, bp + 32);   // coef slots 16..31

    // ---- phase 1a: per-token router weights (softmax over 2 logits) ----
    if (tid < T_TILE) {
        int tg = t0 + tid;
        int tr = (tg < n_tok) ? tg : (n_tok - 1);
        int xi = xg[tr];
        xi = (xi < 0) ? 0 : ((xi >= V) ? V - 1 : xi);   // safety clamp
        sx[tid] = xi;
        bool img = ((tg % SEQ) < SPLIT);
        const float* Wr = img ? WrI : WrT;
        const float* br = img ? brI : brT;
        float l0 = Wr[xi] + br[0];
        float l1 = Wr[(size_t)V + xi] + br[1];
        float w0 = 1.0f / (1.0f + __expf(l1 - l0));
        sw[2 * tid]     = w0;
        sw[2 * tid + 1] = 1.0f - w0;
    }
    __syncthreads();

    // ---- phase 1b: coefficients c[j] = w * 2.0 * A[j][x], stored duplicated ----
    for (int i = tid; i < T_TILE * 32; i += THREADS) {
        int t = i >> 5, j = i & 31;
        int xi = sx[t];
        float c;
        if (j < 16) c = sw[2 * t]     * SCALE * __ldg(A1 + (size_t)j * V + xi);
        else        c = sw[2 * t + 1] * SCALE * __ldg(A2 + (size_t)(j - 16) * V + xi);
        scoef[t * 64 + 2 * j]     = c;
        scoef[t * 64 + 2 * j + 1] = c;
    }
    __syncthreads();

    // ---- phase 2: base gather + rank-32 update via FFMA2, 4-deep pipelined ----
    float4 cur[4], nxt[4];
#pragma unroll
    for (int u = 0; u < 4; ++u)
        cur[u] = *reinterpret_cast<const float4*>(emb + (size_t)sx[u] * DD + d0);

#pragma unroll 1
    for (int g = 0; g < T_TILE; g += 4) {
        // prefetch next group's base rows (keeps ~4 LDG.128/warp in flight)
#pragma unroll
        for (int u = 0; u < 4; ++u) {
            int tn = g + 4 + u;
            if (tn < T_TILE)
                nxt[u] = *reinterpret_cast<const float4*>(emb + (size_t)sx[tn] * DD + d0);
        }
#pragma unroll
        for (int u = 0; u < 4; ++u) {
            const int t = g + u;
            ull acc0 = pk(cur[u].x, cur[u].y);
            ull acc1 = pk(cur[u].z, cur[u].w);
            const ulonglong2* cp = reinterpret_cast<const ulonglong2*>(scoef + t * 64);
#pragma unroll
            for (int j = 0; j < 16; ++j) {          // 2 coef slots per iter (LDS.128 broadcast)
                ulonglong2 cc = cp[j];
                acc0 = fma2(bp[4 * j + 0], cc.x, acc0);
                acc1 = fma2(bp[4 * j + 1], cc.x, acc1);
                acc0 = fma2(bp[4 * j + 2], cc.y, acc0);
                acc1 = fma2(bp[4 * j + 3], cc.y, acc1);
            }
            float o0, o1, o2, o3;
            upk(acc0, o0, o1); upk(acc1, o2, o3);
            if (t0 + t < n_tok)
                *reinterpret_cast<float4*>(out + (size_t)(t0 + t) * DD + d0) =
                    make_float4(o0, o1, o2, o3);
            cur[u] = nxt[u];
        }
    }
}

extern "C" void kernel_launch(void* const* d_in, const int* in_sizes, int n_in,
                              void* d_out, int out_size) {
    const int*   x   = (const int*)d_in[0];
    const float* emb = (const float*)d_in[1];
    const float* A1  = (const float*)d_in[2];
    const float* B1  = (const float*)d_in[3];
    const float* A2  = (const float*)d_in[4];
    const float* B2  = (const float*)d_in[5];
    const float* WrI = (const float*)d_in[6];
    const float* brI = (const float*)d_in[7];
    const float* WrT = (const float*)d_in[8];
    const float* brT = (const float*)d_in[9];
    float* out = (float*)d_out;

    const int E  = in_sizes[7];            // 4
    const int V  = in_sizes[6] / E;        // 32000
    const int BS = in_sizes[0];            // 4096 tokens

    dim3 grid(DD / (4 * THREADS), (BS + T_TILE - 1) / T_TILE);
    moe_emb_kernel<<<grid, THREADS>>>(x, emb, A1, B1, A2, B2,
                                      WrI, brI, WrT, brT, out, V, BS);
}